// round 15
// baseline (speedup 1.0000x reference)
#include <cuda_runtime.h>
#include <cuda_fp16.h>
#include <cstdint>

#define L 4096
#define DE 1024
#define DV 1024
#define HEXP 0.2f
#define DTF (1.0f / 4096.0f)
#define EPSV 1e-8f
#define FFT_N 8192

// ---------------- device scratch (static, no runtime alloc) ----------------
__device__ __half g_Et_h[L * DE];           // E^T fp16 ([l][e])
__device__ __half g_W_h[DV * DE];           // W fp16 ([v][e])
__device__ float g_Yt[(size_t)DV * L];      // Y^T fp32 ([v][l], l contiguous)
__device__ float g_outT[(size_t)DV * L];    // conv result [c][i]
__device__ float2 g_tw[FFT_N];              // exp(-2*pi*i*n/N)
__device__ float2 g_F[FFT_N];               // DIF-ordered FFT(f_padded)/N

// ---------------- helpers ---------------------------------------------------
__device__ __forceinline__ uint32_t smem_u32(const void* p) {
    uint32_t a;
    asm("{ .reg .u64 t; cvta.to.shared.u64 t, %1; cvt.u32.u64 %0, t; }" : "=r"(a) : "l"(p));
    return a;
}
#define SW64(o) ((uint32_t)(o) ^ ((((uint32_t)(o)) >> 3) & 0x30u))

__device__ __forceinline__ void cpasync16(uint32_t dst, const void* src) {
    asm volatile("cp.async.cg.shared.global [%0], [%1], 16;" :: "r"(dst), "l"(src));
}
#define CP_COMMIT() asm volatile("cp.async.commit_group;" ::: "memory")
#define CP_WAIT2()  asm volatile("cp.async.wait_group 2;" ::: "memory")

__device__ __forceinline__ void ldsm4(uint32_t* r, uint32_t addr) {
    asm volatile("ldmatrix.sync.aligned.m8n8.x4.shared.b16 {%0,%1,%2,%3}, [%4];"
                 : "=r"(r[0]), "=r"(r[1]), "=r"(r[2]), "=r"(r[3]) : "r"(addr));
}
__device__ __forceinline__ void mma_fp16(float* c, const uint32_t* a, const uint32_t* b) {
    asm volatile(
        "mma.sync.aligned.m16n8k16.row.col.f32.f16.f16.f32 "
        "{%0,%1,%2,%3}, {%4,%5,%6,%7}, {%8,%9}, {%0,%1,%2,%3};"
        : "+f"(c[0]), "+f"(c[1]), "+f"(c[2]), "+f"(c[3])
        : "r"(a[0]), "r"(a[1]), "r"(a[2]), "r"(a[3]), "r"(b[0]), "r"(b[1]));
}

__device__ __forceinline__ float2 cmul(float2 a, float2 b) {
    return make_float2(a.x * b.x - a.y * b.y, a.x * b.y + a.y * b.x);
}
__device__ __forceinline__ float2 cadd(float2 a, float2 b) { return make_float2(a.x + b.x, a.y + b.y); }
__device__ __forceinline__ float2 csub(float2 a, float2 b) { return make_float2(a.x - b.x, a.y - b.y); }

// ---------------- GEMM tiling: CTA 128x128, 4 warps (64x64 each), BK=32 -----
#define STAGE_BYTES 16384
#define T_A 0
#define T_B 8192
#define GEMM_SMEM (3 * STAGE_BYTES)

__device__ __forceinline__ void fill_tile32(uint32_t dstbase,
                                            const __half* __restrict__ g,
                                            int row0, int k0, int stride, int tid) {
#pragma unroll
    for (int i = 0; i < 4; ++i) {
        int q = tid + i * 128;
        int r = q >> 2, c = q & 3;
        uint32_t o = (uint32_t)(r * 64 + c * 16);
        cpasync16(dstbase + SW64(o), g + (size_t)(row0 + r) * stride + k0 + c * 8);
    }
}

// ---------------- pre-kernels -----------------------------------------------
__global__ void transpose_E_kernel(const float* __restrict__ E) {
    __shared__ float t[64][33];
    int bx = blockIdx.x, by = blockIdx.y;
    int tx = threadIdx.x, ty = threadIdx.y;        // block (32, 8)
#pragma unroll
    for (int i = 0; i < 8; ++i)
        t[ty + 8 * i][tx] = E[(size_t)(by * 64 + ty + 8 * i) * L + bx * 32 + tx];
    __syncthreads();
#pragma unroll
    for (int i = 0; i < 4; ++i) {
        int ll = ty + 8 * i;
        float v0 = t[2 * tx][ll];
        float v1 = t[2 * tx + 1][ll];
        __half2 hp = __halves2half2(__float2half(v0), __float2half(v1));
        size_t o = (size_t)(bx * 32 + ll) * DE + by * 64 + 2 * tx;
        *reinterpret_cast<__half2*>(&g_Et_h[o]) = hp;
    }
}

__global__ void convert_W_kernel(const float* __restrict__ W) {
    int base = (blockIdx.x * 256 + threadIdx.x) * 8;
    uint32_t pk[4];
#pragma unroll
    for (int h = 0; h < 2; ++h) {
        float4 v = *reinterpret_cast<const float4*>(&W[base + 4 * h]);
        __half2 p0 = __halves2half2(__float2half(v.x), __float2half(v.y));
        __half2 p1 = __halves2half2(__float2half(v.z), __float2half(v.w));
        pk[2 * h]     = *reinterpret_cast<uint32_t*>(&p0);
        pk[2 * h + 1] = *reinterpret_cast<uint32_t*>(&p1);
    }
    *reinterpret_cast<uint4*>(&g_W_h[base]) = make_uint4(pk[0], pk[1], pk[2], pk[3]);
}

// ---------------- in-place DIF/DIT radix-8 FFT, skewed smem ------------------
#define PHY(i) ((i) + ((i) >> 4))
#define FFT_BUF 8704
#define C_SQ2 0.70710678118654752f

template <int INV>
__device__ __forceinline__ void dft8_core(float2 t0, float2 t1, float2 t2, float2 t3,
                                          float2 s0, float2 s1, float2 s2, float2 s3,
                                          float2* X) {
    float2 mjt3 = INV ? make_float2(-t3.y, t3.x) : make_float2(t3.y, -t3.x);
    float2 mjs3 = INV ? make_float2(-s3.y, s3.x) : make_float2(s3.y, -s3.x);
    float2 E0 = cadd(t0, t2), E2 = csub(t0, t2);
    float2 E1 = cadd(t1, mjt3), E3 = csub(t1, mjt3);
    float2 O0 = cadd(s0, s2), O2 = csub(s0, s2);
    float2 O1 = cadd(s1, mjs3), O3 = csub(s1, mjs3);
    float2 w1O1 = INV ? make_float2(C_SQ2 * (O1.x - O1.y), C_SQ2 * (O1.x + O1.y))
                      : make_float2(C_SQ2 * (O1.x + O1.y), C_SQ2 * (O1.y - O1.x));
    float2 w2O2 = INV ? make_float2(-O2.y, O2.x) : make_float2(O2.y, -O2.x);
    float2 w3O3 = INV ? make_float2(-C_SQ2 * (O3.x + O3.y), C_SQ2 * (O3.x - O3.y))
                      : make_float2(C_SQ2 * (O3.y - O3.x), -C_SQ2 * (O3.x + O3.y));
    X[0] = cadd(E0, O0);   X[4] = csub(E0, O0);
    X[1] = cadd(E1, w1O1); X[5] = csub(E1, w1O1);
    X[2] = cadd(E2, w2O2); X[6] = csub(E2, w2O2);
    X[3] = cadd(E3, w3O3); X[7] = csub(E3, w3O3);
}

// forward DIF radix-8 stage, in-place.  FACTOR = FFT_N/(8*M).
template <int NT, int M, int FACTOR>
__device__ __forceinline__ void dif8_stage(float2* X, int tid) {
#pragma unroll
    for (int it = 0; it < 1024 / NT; ++it) {
        int bf = tid + it * NT;
        int i = bf & (M - 1);
        int p = (bf & ~(M - 1)) * 8 + i;
        float2 x[8];
#pragma unroll
        for (int j = 0; j < 8; ++j) x[j] = X[PHY(p + j * M)];
        float2 Xo[8];
        dft8_core<0>(cadd(x[0], x[4]), csub(x[0], x[4]), cadd(x[2], x[6]), csub(x[2], x[6]),
                     cadd(x[1], x[5]), csub(x[1], x[5]), cadd(x[3], x[7]), csub(x[3], x[7]), Xo);
        X[PHY(p)] = Xo[0];
#pragma unroll
        for (int j = 1; j < 8; ++j)
            X[PHY(p + j * M)] = cmul(g_tw[j * i * FACTOR], Xo[j]);
    }
    __syncthreads();
}

// inverse DIT radix-8 stage, in-place.
template <int NT, int M, int FACTOR>
__device__ __forceinline__ void dit8_stage(float2* X, int tid) {
#pragma unroll
    for (int it = 0; it < 1024 / NT; ++it) {
        int bf = tid + it * NT;
        int i = bf & (M - 1);
        int p = (bf & ~(M - 1)) * 8 + i;
        float2 t[8];
        t[0] = X[PHY(p)];
#pragma unroll
        for (int j = 1; j < 8; ++j) {
            float2 w = g_tw[j * i * FACTOR];
            w.y = -w.y;
            t[j] = cmul(w, X[PHY(p + j * M)]);
        }
        float2 Xo[8];
        dft8_core<1>(cadd(t[0], t[4]), csub(t[0], t[4]), cadd(t[2], t[6]), csub(t[2], t[6]),
                     cadd(t[1], t[5]), csub(t[1], t[5]), cadd(t[3], t[7]), csub(t[3], t[7]), Xo);
#pragma unroll
        for (int j = 0; j < 8; ++j) X[PHY(p + j * M)] = Xo[j];
    }
    __syncthreads();
}

// fft_F: single CTA; computes g_tw, DIF-forward of f (same pipeline as conv),
// stores spectrum (x 1/N) in DIF storage order -> g_F.
__global__ __launch_bounds__(256) void fft_F_kernel() {
    extern __shared__ float2 X[];
    int tid = threadIdx.x;
#pragma unroll
    for (int it = 0; it < 32; ++it) {
        int n = tid + it * 256;
        float s, c;
        sincospif(-2.0f * (float)n / (float)FFT_N, &s, &c);
        g_tw[n] = make_float2(c, s);
    }
    __syncthreads();
    // stage 1 (M=1024, FACTOR=1): f values computed in registers; upper half zero
#pragma unroll
    for (int it = 0; it < 4; ++it) {
        int bf = tid + it * 256;
        float f0 = (bf == 0) ? powf(EPSV, HEXP) : powf((float)bf * DTF + EPSV, HEXP);
        float f1 = powf((float)(bf + 1024) * DTF + EPSV, HEXP);
        float f2 = powf((float)(bf + 2048) * DTF + EPSV, HEXP);
        float f3 = powf((float)(bf + 3072) * DTF + EPSV, HEXP);
        float2 x0 = make_float2(f0, 0.f), x1 = make_float2(f1, 0.f);
        float2 x2 = make_float2(f2, 0.f), x3 = make_float2(f3, 0.f);
        float2 Xo[8];
        dft8_core<0>(x0, x0, x2, x2, x1, x1, x3, x3, Xo);
        X[PHY(bf)] = Xo[0];
#pragma unroll
        for (int j = 1; j < 8; ++j)
            X[PHY(bf + j * 1024)] = cmul(g_tw[j * bf], Xo[j]);
    }
    __syncthreads();
    dif8_stage<256, 128, 8>(X, tid);
    dif8_stage<256, 16, 64>(X, tid);
    dif8_stage<256, 2, 512>(X, tid);
    // final forward r2 (pairs 2q,2q+1, twiddle 1) + 1/N scale -> g_F
    const float scale = 1.0f / (float)FFT_N;
#pragma unroll
    for (int it = 0; it < 16; ++it) {
        int q = tid + it * 256;
        float2 u = X[PHY(2 * q)];
        float2 v = X[PHY(2 * q + 1)];
        float2 lo = cadd(u, v);
        float2 hi = csub(u, v);
        g_F[2 * q]     = make_float2(lo.x * scale, lo.y * scale);
        g_F[2 * q + 1] = make_float2(hi.x * scale, hi.y * scale);
    }
}

// ---------------- conv: in-place DIF fwd -> xF -> DIT inv, one 68KB buffer ---
#define CONV_NT 256
__global__ __launch_bounds__(CONV_NT) void conv_kernel() {
    extern __shared__ float2 X[];
    int tid = threadIdx.x;
    int c2 = blockIdx.x * 2;
    const float* __restrict__ ya = g_Yt + (size_t)c2 * L;
    const float* __restrict__ yb = g_Yt + (size_t)(c2 + 1) * L;

    // fwd DIF stage M=1024 straight from global; upper half (j>=4) is zero
#pragma unroll
    for (int it = 0; it < 1024 / CONV_NT; ++it) {
        int bf = tid + it * CONV_NT;
        float2 x0 = make_float2(ya[bf], yb[bf]);
        float2 x1 = make_float2(ya[bf + 1024], yb[bf + 1024]);
        float2 x2 = make_float2(ya[bf + 2048], yb[bf + 2048]);
        float2 x3 = make_float2(ya[bf + 3072], yb[bf + 3072]);
        float2 Xo[8];
        dft8_core<0>(x0, x0, x2, x2, x1, x1, x3, x3, Xo);
        X[PHY(bf)] = Xo[0];
#pragma unroll
        for (int j = 1; j < 8; ++j)
            X[PHY(bf + j * 1024)] = cmul(g_tw[j * bf], Xo[j]);
    }
    __syncthreads();
    dif8_stage<CONV_NT, 128, 8>(X, tid);
    dif8_stage<CONV_NT, 16, 64>(X, tid);
    dif8_stage<CONV_NT, 2, 512>(X, tid);
    // fused: fwd r2 -> x F (DIF order) -> inv r2, same adjacent pairs, one pass
#pragma unroll
    for (int it = 0; it < 4096 / CONV_NT; ++it) {
        int q = tid + it * CONV_NT;
        float2 u = X[PHY(2 * q)];
        float2 v = X[PHY(2 * q + 1)];
        float2 a = cmul(cadd(u, v), g_F[2 * q]);
        float2 b = cmul(csub(u, v), g_F[2 * q + 1]);
        X[PHY(2 * q)] = cadd(a, b);
        X[PHY(2 * q + 1)] = csub(a, b);
    }
    __syncthreads();
    dit8_stage<CONV_NT, 2, 512>(X, tid);
    dit8_stage<CONV_NT, 16, 64>(X, tid);
    dit8_stage<CONV_NT, 128, 8>(X, tid);
    // inv DIT final stage M=1024: natural-order outputs; only k < 4096 (j<4)
    float* __restrict__ oa = g_outT + (size_t)c2 * L;
    float* __restrict__ ob = g_outT + (size_t)(c2 + 1) * L;
#pragma unroll
    for (int it = 0; it < 1024 / CONV_NT; ++it) {
        int bf = tid + it * CONV_NT;
        float2 t[8];
        t[0] = X[PHY(bf)];
#pragma unroll
        for (int j = 1; j < 8; ++j) {
            float2 w = g_tw[j * bf];
            w.y = -w.y;
            t[j] = cmul(w, X[PHY(bf + j * 1024)]);
        }
        float2 Xo[8];
        dft8_core<1>(cadd(t[0], t[4]), csub(t[0], t[4]), cadd(t[2], t[6]), csub(t[2], t[6]),
                     cadd(t[1], t[5]), csub(t[1], t[5]), cadd(t[3], t[7]), csub(t[3], t[7]), Xo);
#pragma unroll
        for (int j = 0; j < 4; ++j) {
            int k = bf + j * 1024;
            oa[k] = Xo[j].x;
            ob[k] = Xo[j].y;
        }
    }
}

// g_outT [c][i] -> out [i][c]; 64x64 tile, float2 both directions
__global__ void transpose_out_kernel(float* __restrict__ out) {
    __shared__ float2 t2[64][33];
    int i0 = blockIdx.x * 64, c0 = blockIdx.y * 64;
    int tx = threadIdx.x, ty = threadIdx.y;  // (32, 8)
#pragma unroll
    for (int k = 0; k < 8; ++k) {
        int r = ty + 8 * k;
        t2[r][tx] = *reinterpret_cast<const float2*>(&g_outT[(size_t)(c0 + r) * L + i0 + 2 * tx]);
    }
    __syncthreads();
#pragma unroll
    for (int k = 0; k < 8; ++k) {
        int r = ty + 8 * k;
        float2 p0 = t2[2 * tx][r >> 1];
        float2 p1 = t2[2 * tx + 1][r >> 1];
        float2 o;
        o.x = (r & 1) ? p0.y : p0.x;
        o.y = (r & 1) ? p1.y : p1.x;
        *reinterpret_cast<float2*>(&out[(size_t)(i0 + r) * DV + c0 + 2 * tx]) = o;
    }
}

// ---------------- GEMM1 compute: single fp16, warp tile 64x64 ----------------
__device__ __forceinline__ void compute_stage64(uint32_t sbase, int lane, int wm, int wn,
                                                float acc[4][8][4]) {
    const int arow = lane & 15;
    const int acolb = (lane >> 4) << 4;
    const int brow = (lane & 7) + ((lane >> 4) << 3);
    const int bcolb = ((lane >> 3) & 1) << 4;
#pragma unroll
    for (int kk = 0; kk < 2; ++kk) {
        uint32_t aF[4][4];
#pragma unroll
        for (int mi = 0; mi < 4; ++mi) {
            uint32_t o = SW64((uint32_t)((wm * 64 + mi * 16 + arow) * 64 + acolb)) ^ (kk << 5);
            ldsm4(aF[mi], sbase + T_A + o);
        }
#pragma unroll
        for (int pi = 0; pi < 4; ++pi) {
            uint32_t bF[4];
            uint32_t o = SW64((uint32_t)((wn * 64 + pi * 16 + brow) * 64 + bcolb)) ^ (kk << 5);
            ldsm4(bF, sbase + T_B + o);
#pragma unroll
            for (int mi = 0; mi < 4; ++mi)
#pragma unroll
                for (int q = 0; q < 2; ++q)
                    mma_fp16(acc[mi][pi * 2 + q], aF[mi], &bF[q * 2]);
        }
    }
}

__global__ __launch_bounds__(128, 2) void gemm1_mma() {
    extern __shared__ char smem[];
    const uint32_t sb = smem_u32(smem);
    const int tid = threadIdx.x, lane = tid & 31, wid = tid >> 5;
    const int wm = wid & 1, wn = (wid >> 1) & 1;
    const int l0 = blockIdx.x * 128;
    const int v0 = blockIdx.y * 128;
    const int KT = DE / 32;

    float acc[4][8][4];
#pragma unroll
    for (int mi = 0; mi < 4; ++mi)
#pragma unroll
        for (int ni = 0; ni < 8; ++ni)
#pragma unroll
            for (int r = 0; r < 4; ++r) acc[mi][ni][r] = 0.f;

#pragma unroll
    for (int s = 0; s < 2; ++s) {
        uint32_t st = sb + s * STAGE_BYTES;
        int k0 = s * 32;
        fill_tile32(st + T_A, g_W_h,  v0, k0, DE, tid);
        fill_tile32(st + T_B, g_Et_h, l0, k0, DE, tid);
        CP_COMMIT();
    }
    for (int kt = 0; kt < KT; ++kt) {
        int ls = kt + 2;
        if (ls < KT) {
            uint32_t st = sb + (ls % 3) * STAGE_BYTES;
            int k0 = ls * 32;
            fill_tile32(st + T_A, g_W_h,  v0, k0, DE, tid);
            fill_tile32(st + T_B, g_Et_h, l0, k0, DE, tid);
        }
        CP_COMMIT();
        CP_WAIT2();
        __syncthreads();
        compute_stage64(sb + (kt % 3) * STAGE_BYTES, lane, wm, wn, acc);
        __syncthreads();
    }

#pragma unroll
    for (int mi = 0; mi < 4; ++mi)
#pragma unroll
        for (int ni = 0; ni < 8; ++ni) {
            const float* c = acc[mi][ni];
            int v_ = v0 + wm * 64 + mi * 16 + (lane >> 2);
            int l_ = l0 + wn * 64 + ni * 8 + 2 * (lane & 3);
#pragma unroll
            for (int h = 0; h < 2; ++h) {
                float2 p;
                p.x = c[2 * h];
                p.y = c[2 * h + 1];
                *reinterpret_cast<float2*>(&g_Yt[(size_t)(v_ + 8 * h) * L + l_]) = p;
            }
        }
}

// ---------------------------------------------------------------------------
#define FFT_SMEM (FFT_BUF * (int)sizeof(float2))

extern "C" void kernel_launch(void* const* d_in, const int* in_sizes, int n_in,
                              void* d_out, int out_size) {
    const float* E = (const float*)d_in[0];   // (1024, 4096)
    const float* W = (const float*)d_in[1];   // (1024, 1024)
    float* out = (float*)d_out;               // (4096, 1024)

    cudaFuncSetAttribute(gemm1_mma, cudaFuncAttributeMaxDynamicSharedMemorySize, GEMM_SMEM);
    cudaFuncSetAttribute(fft_F_kernel, cudaFuncAttributeMaxDynamicSharedMemorySize, FFT_SMEM);
    cudaFuncSetAttribute(conv_kernel, cudaFuncAttributeMaxDynamicSharedMemorySize, FFT_SMEM);

    fft_F_kernel<<<1, 256, FFT_SMEM>>>();
    transpose_E_kernel<<<dim3(L / 32, DE / 64), dim3(32, 8)>>>(E);
    convert_W_kernel<<<(DV * DE) / (256 * 8), 256>>>(W);
    gemm1_mma<<<dim3(L / 128, DV / 128), 128, GEMM_SMEM>>>();
    conv_kernel<<<DV / 2, CONV_NT, FFT_SMEM>>>();
    transpose_out_kernel<<<dim3(L / 64, DV / 64), dim3(32, 8)>>>(out);
}

// round 16
// speedup vs baseline: 1.1543x; 1.1543x over previous
#include <cuda_runtime.h>
#include <cuda_fp16.h>
#include <cstdint>

#define L 4096
#define DE 1024
#define DV 1024
#define HEXP 0.2f
#define DTF (1.0f / 4096.0f)
#define EPSV 1e-8f
#define FFT_N 8192

// ---------------- device scratch (static, no runtime alloc) ----------------
__device__ __half g_Et_h[L * DE];           // E^T fp16 ([l][e])
__device__ __half g_W_h[DV * DE];           // W fp16 ([v][e])
__device__ float g_Yt[(size_t)DV * L];      // Y^T fp32 ([v][l], l contiguous)
__device__ float g_outT[(size_t)DV * L];    // conv result [c][i]
__device__ float2 g_tw[FFT_N];              // exp(-2*pi*i*n/N)
__device__ float2 g_F[FFT_N];               // FFT(f_padded)/N

// ---------------- helpers ---------------------------------------------------
__device__ __forceinline__ uint32_t smem_u32(const void* p) {
    uint32_t a;
    asm("{ .reg .u64 t; cvta.to.shared.u64 t, %1; cvt.u32.u64 %0, t; }" : "=r"(a) : "l"(p));
    return a;
}
#define SW128(o) ((uint32_t)(o) ^ ((((uint32_t)(o)) >> 3) & 0x70u))

__device__ __forceinline__ void cpasync16(uint32_t dst, const void* src) {
    asm volatile("cp.async.cg.shared.global [%0], [%1], 16;" :: "r"(dst), "l"(src));
}
#define CP_COMMIT() asm volatile("cp.async.commit_group;" ::: "memory")
#define CP_WAIT2()  asm volatile("cp.async.wait_group 2;" ::: "memory")

__device__ __forceinline__ void ldsm4(uint32_t* r, uint32_t addr) {
    asm volatile("ldmatrix.sync.aligned.m8n8.x4.shared.b16 {%0,%1,%2,%3}, [%4];"
                 : "=r"(r[0]), "=r"(r[1]), "=r"(r[2]), "=r"(r[3]) : "r"(addr));
}
__device__ __forceinline__ void mma_fp16(float* c, const uint32_t* a, const uint32_t* b) {
    asm volatile(
        "mma.sync.aligned.m16n8k16.row.col.f32.f16.f16.f32 "
        "{%0,%1,%2,%3}, {%4,%5,%6,%7}, {%8,%9}, {%0,%1,%2,%3};"
        : "+f"(c[0]), "+f"(c[1]), "+f"(c[2]), "+f"(c[3])
        : "r"(a[0]), "r"(a[1]), "r"(a[2]), "r"(a[3]), "r"(b[0]), "r"(b[1]));
}

__device__ __forceinline__ float2 cmul(float2 a, float2 b) {
    return make_float2(a.x * b.x - a.y * b.y, a.x * b.y + a.y * b.x);
}
__device__ __forceinline__ float2 cadd(float2 a, float2 b) { return make_float2(a.x + b.x, a.y + b.y); }
__device__ __forceinline__ float2 csub(float2 a, float2 b) { return make_float2(a.x - b.x, a.y - b.y); }

// ---------------- GEMM tiling: CTA 128x128, 4 warps (64x64 each), BK=64 -----
// Per stage: W(16K) Et(16K) = 32KB.  3 stages = 96KB.  2 CTAs/SM = 192KB.
#define STAGE_BYTES 32768
#define T_A 0
#define T_B 16384
#define GEMM_SMEM (3 * STAGE_BYTES)

// fill 128x64 fp16 k-major tile (128B rows, SW128) via cp.async; 128 thr, 8 iters
__device__ __forceinline__ void fill_tile64(uint32_t dstbase,
                                            const __half* __restrict__ g,
                                            int row0, int k0, int stride, int tid) {
#pragma unroll
    for (int i = 0; i < 8; ++i) {
        int q = tid + i * 128;
        int r = q >> 3, c = q & 7;
        uint32_t o = (uint32_t)(r * 128 + c * 16);
        cpasync16(dstbase + SW128(o), g + (size_t)(row0 + r) * stride + k0 + c * 8);
    }
}

// ---------------- pre-kernels -----------------------------------------------
__global__ void transpose_E_kernel(const float* __restrict__ E) {
    __shared__ float t[64][33];
    int bx = blockIdx.x, by = blockIdx.y;
    int tx = threadIdx.x, ty = threadIdx.y;        // block (32, 8)
#pragma unroll
    for (int i = 0; i < 8; ++i)
        t[ty + 8 * i][tx] = E[(size_t)(by * 64 + ty + 8 * i) * L + bx * 32 + tx];
    __syncthreads();
#pragma unroll
    for (int i = 0; i < 4; ++i) {
        int ll = ty + 8 * i;
        float v0 = t[2 * tx][ll];
        float v1 = t[2 * tx + 1][ll];
        __half2 hp = __halves2half2(__float2half(v0), __float2half(v1));
        size_t o = (size_t)(bx * 32 + ll) * DE + by * 64 + 2 * tx;
        *reinterpret_cast<__half2*>(&g_Et_h[o]) = hp;
    }
}

__global__ void convert_W_kernel(const float* __restrict__ W) {
    int base = (blockIdx.x * 256 + threadIdx.x) * 8;
    uint32_t pk[4];
#pragma unroll
    for (int h = 0; h < 2; ++h) {
        float4 v = *reinterpret_cast<const float4*>(&W[base + 4 * h]);
        __half2 p0 = __halves2half2(__float2half(v.x), __float2half(v.y));
        __half2 p1 = __halves2half2(__float2half(v.z), __float2half(v.w));
        pk[2 * h]     = *reinterpret_cast<uint32_t*>(&p0);
        pk[2 * h + 1] = *reinterpret_cast<uint32_t*>(&p1);
    }
    *reinterpret_cast<uint4*>(&g_W_h[base]) = make_uint4(pk[0], pk[1], pk[2], pk[3]);
}

// ---------------- radix-8 Stockham FFT, skewed smem (R14 proven) -------------
#define PHY(i) ((i) + ((i) >> 4))
#define FFT_BUF 8704
#define C_SQ2 0.70710678118654752f

template <int INV>
__device__ __forceinline__ void dft8_store(float2* dst, int u, int k, int m,
                                           float2 t0, float2 t1, float2 t2, float2 t3,
                                           float2 s0, float2 s1, float2 s2, float2 s3) {
    float2 mjt3 = INV ? make_float2(-t3.y, t3.x) : make_float2(t3.y, -t3.x);
    float2 mjs3 = INV ? make_float2(-s3.y, s3.x) : make_float2(s3.y, -s3.x);
    float2 E0 = cadd(t0, t2), E2 = csub(t0, t2);
    float2 E1 = cadd(t1, mjt3), E3 = csub(t1, mjt3);
    float2 O0 = cadd(s0, s2), O2 = csub(s0, s2);
    float2 O1 = cadd(s1, mjs3), O3 = csub(s1, mjs3);
    float2 w1O1 = INV ? make_float2(C_SQ2 * (O1.x - O1.y), C_SQ2 * (O1.x + O1.y))
                      : make_float2(C_SQ2 * (O1.x + O1.y), C_SQ2 * (O1.y - O1.x));
    float2 w2O2 = INV ? make_float2(-O2.y, O2.x) : make_float2(O2.y, -O2.x);
    float2 w3O3 = INV ? make_float2(-C_SQ2 * (O3.x + O3.y), C_SQ2 * (O3.x - O3.y))
                      : make_float2(C_SQ2 * (O3.y - O3.x), -C_SQ2 * (O3.x + O3.y));
    float2 X[8];
    X[0] = cadd(E0, O0);   X[4] = csub(E0, O0);
    X[1] = cadd(E1, w1O1); X[5] = csub(E1, w1O1);
    X[2] = cadd(E2, w2O2); X[6] = csub(E2, w2O2);
    X[3] = cadd(E3, w3O3); X[7] = csub(E3, w3O3);
    int b8 = 8 * u + k;
    dst[PHY(b8)] = X[0];
#pragma unroll
    for (int j = 1; j < 8; ++j) {
        float2 w = g_tw[j * u];
        if (INV) w.y = -w.y;
        dst[PHY(b8 + j * m)] = cmul(w, X[j]);
    }
}

template <int NT, int INV>
__device__ __forceinline__ void r8_stage(const float2* src, float2* dst, int tid, int m) {
#pragma unroll
    for (int it = 0; it < 1024 / NT; ++it) {
        int bf = tid + it * NT;
        int k = bf & (m - 1);
        int u = bf - k;
        float2 x0 = src[PHY(bf)];
        float2 x1 = src[PHY(bf + 1024)];
        float2 x2 = src[PHY(bf + 2048)];
        float2 x3 = src[PHY(bf + 3072)];
        float2 x4 = src[PHY(bf + 4096)];
        float2 x5 = src[PHY(bf + 5120)];
        float2 x6 = src[PHY(bf + 6144)];
        float2 x7 = src[PHY(bf + 7168)];
        dft8_store<INV>(dst, u, k, m,
                        cadd(x0, x4), csub(x0, x4), cadd(x2, x6), csub(x2, x6),
                        cadd(x1, x5), csub(x1, x5), cadd(x3, x7), csub(x3, x7));
    }
    __syncthreads();
}

// fft_F: single CTA; computes g_tw, FFT of f, writes g_F.
__global__ __launch_bounds__(256) void fft_F_kernel() {
    extern __shared__ float2 sm[];
    float2* A = sm;
    float2* B = sm + FFT_BUF;
    int tid = threadIdx.x;
#pragma unroll
    for (int it = 0; it < 32; ++it) {
        int n = tid + it * 256;
        float s, c;
        sincospif(-2.0f * (float)n / (float)FFT_N, &s, &c);
        g_tw[n] = make_float2(c, s);
    }
#pragma unroll
    for (int it = 0; it < 32; ++it) {
        int d = tid + it * 256;
        float v = 0.f;
        if (d < L) {
            float base = (d == 0) ? EPSV : ((float)d * DTF + EPSV);
            v = powf(base, HEXP);
        }
        A[PHY(d)] = make_float2(v, 0.f);
    }
    __syncthreads();
    {
        float2* src = A;
        float2* dst = B;
        int m = 1;
#pragma unroll 1
        for (int s = 0; s < 4; ++s) {
            r8_stage<256, 0>(src, dst, tid, m);
            float2* t = src; src = dst; dst = t;
            m <<= 3;
        }
        const float scale = 1.0f / (float)FFT_N;
#pragma unroll
        for (int it = 0; it < 16; ++it) {
            int k = tid + it * 256;
            float2 a = src[PHY(k)];
            float2 b = src[PHY(k + FFT_N / 2)];
            float2 lo = cadd(a, b);
            float2 hi = csub(a, b);
            g_F[k] = make_float2(lo.x * scale, lo.y * scale);
            g_F[k + FFT_N / 2] = make_float2(hi.x * scale, hi.y * scale);
        }
    }
}

// ---------------- conv: fused, zero-pad-aware, half-output, NT=512 (R14) -----
#define CONV_NT 512
__global__ __launch_bounds__(CONV_NT) void conv_kernel() {
    extern __shared__ float2 sm[];
    float2* A = sm;
    float2* B = sm + FFT_BUF;
    int tid = threadIdx.x;
    int c2 = blockIdx.x * 2;
    const float* __restrict__ ya = g_Yt + (size_t)c2 * L;
    const float* __restrict__ yb = g_Yt + (size_t)(c2 + 1) * L;

#pragma unroll
    for (int it = 0; it < 1024 / CONV_NT; ++it) {
        int bf = tid + it * CONV_NT;
        float2 x0 = make_float2(ya[bf], yb[bf]);
        float2 x1 = make_float2(ya[bf + 1024], yb[bf + 1024]);
        float2 x2 = make_float2(ya[bf + 2048], yb[bf + 2048]);
        float2 x3 = make_float2(ya[bf + 3072], yb[bf + 3072]);
        dft8_store<0>(A, bf, 0, 1, x0, x0, x2, x2, x1, x1, x3, x3);
    }
    __syncthreads();
    r8_stage<CONV_NT, 0>(A, B, tid, 8);
    r8_stage<CONV_NT, 0>(B, A, tid, 64);
    r8_stage<CONV_NT, 0>(A, B, tid, 512);
#pragma unroll
    for (int it = 0; it < 4096 / CONV_NT; ++it) {
        int k = tid + it * CONV_NT;
        float2 a = B[PHY(k)];
        float2 b = B[PHY(k + FFT_N / 2)];
        A[PHY(k)] = cmul(cadd(a, b), g_F[k]);
        A[PHY(k + FFT_N / 2)] = cmul(csub(a, b), g_F[k + FFT_N / 2]);
    }
    __syncthreads();
    r8_stage<CONV_NT, 1>(A, B, tid, 1);
    r8_stage<CONV_NT, 1>(B, A, tid, 8);
    r8_stage<CONV_NT, 1>(A, B, tid, 64);
    r8_stage<CONV_NT, 1>(B, A, tid, 512);
    float* __restrict__ oa = g_outT + (size_t)c2 * L;
    float* __restrict__ ob = g_outT + (size_t)(c2 + 1) * L;
#pragma unroll
    for (int it = 0; it < 4096 / CONV_NT; ++it) {
        int k = tid + it * CONV_NT;
        float2 a = A[PHY(k)];
        float2 b = A[PHY(k + FFT_N / 2)];
        float2 s = cadd(a, b);
        oa[k] = s.x;
        ob[k] = s.y;
    }
}

// g_outT [c][i] -> out [i][c]; 64x64 tile, float2 both directions
__global__ void transpose_out_kernel(float* __restrict__ out) {
    __shared__ float2 t2[64][33];
    int i0 = blockIdx.x * 64, c0 = blockIdx.y * 64;
    int tx = threadIdx.x, ty = threadIdx.y;  // (32, 8)
#pragma unroll
    for (int k = 0; k < 8; ++k) {
        int r = ty + 8 * k;
        t2[r][tx] = *reinterpret_cast<const float2*>(&g_outT[(size_t)(c0 + r) * L + i0 + 2 * tx]);
    }
    __syncthreads();
#pragma unroll
    for (int k = 0; k < 8; ++k) {
        int r = ty + 8 * k;
        float2 p0 = t2[2 * tx][r >> 1];
        float2 p1 = t2[2 * tx + 1][r >> 1];
        float2 o;
        o.x = (r & 1) ? p0.y : p0.x;
        o.y = (r & 1) ? p1.y : p1.x;
        *reinterpret_cast<float2*>(&out[(size_t)(i0 + r) * DV + c0 + 2 * tx]) = o;
    }
}

// ---------------- GEMM1 compute: single fp16, warp 64x64, BK=64 --------------
__device__ __forceinline__ void compute_stage64(uint32_t sbase, int lane, int wm, int wn,
                                                float acc[4][8][4]) {
    const int arow = lane & 15;
    const int acolb = (lane >> 4) << 4;
    const int brow = (lane & 7) + ((lane >> 4) << 3);
    const int bcolb = ((lane >> 3) & 1) << 4;
#pragma unroll
    for (int kk = 0; kk < 4; ++kk) {
        uint32_t aF[4][4];
#pragma unroll
        for (int mi = 0; mi < 4; ++mi) {
            uint32_t o = SW128((uint32_t)((wm * 64 + mi * 16 + arow) * 128 + acolb)) ^ (kk << 5);
            ldsm4(aF[mi], sbase + T_A + o);
        }
#pragma unroll
        for (int pi = 0; pi < 4; ++pi) {
            uint32_t bF[4];
            uint32_t o = SW128((uint32_t)((wn * 64 + pi * 16 + brow) * 128 + bcolb)) ^ (kk << 5);
            ldsm4(bF, sbase + T_B + o);
#pragma unroll
            for (int mi = 0; mi < 4; ++mi)
#pragma unroll
                for (int q = 0; q < 2; ++q)
                    mma_fp16(acc[mi][pi * 2 + q], aF[mi], &bF[q * 2]);
        }
    }
}

// GEMM1: Yt[v][l] = sum_e W[v][e] * Et[l][e];  A = W (fp16), B = Et (fp16)
__global__ __launch_bounds__(128, 2) void gemm1_mma() {
    extern __shared__ char smem[];
    const uint32_t sb = smem_u32(smem);
    const int tid = threadIdx.x, lane = tid & 31, wid = tid >> 5;
    const int wm = wid & 1, wn = (wid >> 1) & 1;
    const int l0 = blockIdx.x * 128;
    const int v0 = blockIdx.y * 128;
    const int KT = DE / 64;

    float acc[4][8][4];
#pragma unroll
    for (int mi = 0; mi < 4; ++mi)
#pragma unroll
        for (int ni = 0; ni < 8; ++ni)
#pragma unroll
            for (int r = 0; r < 4; ++r) acc[mi][ni][r] = 0.f;

#pragma unroll
    for (int s = 0; s < 2; ++s) {
        uint32_t st = sb + s * STAGE_BYTES;
        int k0 = s * 64;
        fill_tile64(st + T_A, g_W_h,  v0, k0, DE, tid);
        fill_tile64(st + T_B, g_Et_h, l0, k0, DE, tid);
        CP_COMMIT();
    }
    for (int kt = 0; kt < KT; ++kt) {
        int ls = kt + 2;
        if (ls < KT) {
            uint32_t st = sb + (ls % 3) * STAGE_BYTES;
            int k0 = ls * 64;
            fill_tile64(st + T_A, g_W_h,  v0, k0, DE, tid);
            fill_tile64(st + T_B, g_Et_h, l0, k0, DE, tid);
        }
        CP_COMMIT();
        CP_WAIT2();
        __syncthreads();
        compute_stage64(sb + (kt % 3) * STAGE_BYTES, lane, wm, wn, acc);
        __syncthreads();
    }

#pragma unroll
    for (int mi = 0; mi < 4; ++mi)
#pragma unroll
        for (int ni = 0; ni < 8; ++ni) {
            const float* c = acc[mi][ni];
            int v_ = v0 + wm * 64 + mi * 16 + (lane >> 2);
            int l_ = l0 + wn * 64 + ni * 8 + 2 * (lane & 3);
#pragma unroll
            for (int h = 0; h < 2; ++h) {
                float2 p;
                p.x = c[2 * h];
                p.y = c[2 * h + 1];
                *reinterpret_cast<float2*>(&g_Yt[(size_t)(v_ + 8 * h) * L + l_]) = p;
            }
        }
}

// ---------------------------------------------------------------------------
#define FFT_SMEM (2 * FFT_BUF * (int)sizeof(float2))

extern "C" void kernel_launch(void* const* d_in, const int* in_sizes, int n_in,
                              void* d_out, int out_size) {
    const float* E = (const float*)d_in[0];   // (1024, 4096)
    const float* W = (const float*)d_in[1];   // (1024, 1024)
    float* out = (float*)d_out;               // (4096, 1024)

    cudaFuncSetAttribute(gemm1_mma, cudaFuncAttributeMaxDynamicSharedMemorySize, GEMM_SMEM);
    cudaFuncSetAttribute(fft_F_kernel, cudaFuncAttributeMaxDynamicSharedMemorySize, FFT_SMEM);
    cudaFuncSetAttribute(conv_kernel, cudaFuncAttributeMaxDynamicSharedMemorySize, FFT_SMEM);

    fft_F_kernel<<<1, 256, FFT_SMEM>>>();
    transpose_E_kernel<<<dim3(L / 32, DE / 64), dim3(32, 8)>>>(E);
    convert_W_kernel<<<(DV * DE) / (256 * 8), 256>>>(W);
    gemm1_mma<<<dim3(L / 128, DV / 128), 128, GEMM_SMEM>>>();
    conv_kernel<<<DV / 2, CONV_NT, FFT_SMEM>>>();
    transpose_out_kernel<<<dim3(L / 64, DV / 64), dim3(32, 8)>>>(out);
}

// round 17
// speedup vs baseline: 1.2660x; 1.0967x over previous
#include <cuda_runtime.h>
#include <cuda_fp16.h>
#include <cstdint>

#define L 4096
#define DE 1024
#define DV 1024
#define HEXP 0.2f
#define DTF (1.0f / 4096.0f)
#define EPSV 1e-8f
#define FFT_N 8192

// ---------------- device scratch (static, no runtime alloc) ----------------
__device__ __half g_Et_h[L * DE];           // E^T fp16 ([l][e])
__device__ __half g_W_h[DV * DE];           // W fp16 ([v][e])
__device__ float g_Yt[(size_t)DV * L];      // Y^T fp32 ([v][l], l contiguous)
__device__ float g_outT[(size_t)DV * L];    // conv result [c][i]
__device__ float2 g_tw[FFT_N];              // exp(-2*pi*i*n/N)
__device__ float2 g_F[FFT_N];               // FFT(f_padded)/N, pipeline order

// ---------------- helpers ---------------------------------------------------
__device__ __forceinline__ uint32_t smem_u32(const void* p) {
    uint32_t a;
    asm("{ .reg .u64 t; cvta.to.shared.u64 t, %1; cvt.u32.u64 %0, t; }" : "=r"(a) : "l"(p));
    return a;
}
#define SW128(o) ((uint32_t)(o) ^ ((((uint32_t)(o)) >> 3) & 0x70u))

__device__ __forceinline__ void cpasync16(uint32_t dst, const void* src) {
    asm volatile("cp.async.cg.shared.global [%0], [%1], 16;" :: "r"(dst), "l"(src));
}
#define CP_COMMIT() asm volatile("cp.async.commit_group;" ::: "memory")
#define CP_WAIT2()  asm volatile("cp.async.wait_group 2;" ::: "memory")

__device__ __forceinline__ void ldsm4(uint32_t* r, uint32_t addr) {
    asm volatile("ldmatrix.sync.aligned.m8n8.x4.shared.b16 {%0,%1,%2,%3}, [%4];"
                 : "=r"(r[0]), "=r"(r[1]), "=r"(r[2]), "=r"(r[3]) : "r"(addr));
}
__device__ __forceinline__ void mma_fp16(float* c, const uint32_t* a, const uint32_t* b) {
    asm volatile(
        "mma.sync.aligned.m16n8k16.row.col.f32.f16.f16.f32 "
        "{%0,%1,%2,%3}, {%4,%5,%6,%7}, {%8,%9}, {%0,%1,%2,%3};"
        : "+f"(c[0]), "+f"(c[1]), "+f"(c[2]), "+f"(c[3])
        : "r"(a[0]), "r"(a[1]), "r"(a[2]), "r"(a[3]), "r"(b[0]), "r"(b[1]));
}

__device__ __forceinline__ float2 cmul(float2 a, float2 b) {
    return make_float2(a.x * b.x - a.y * b.y, a.x * b.y + a.y * b.x);
}
__device__ __forceinline__ float2 cadd(float2 a, float2 b) { return make_float2(a.x + b.x, a.y + b.y); }
__device__ __forceinline__ float2 csub(float2 a, float2 b) { return make_float2(a.x - b.x, a.y - b.y); }

// ---------------- GEMM tiling: CTA 128x128, 4 warps (64x64 each), BK=64 -----
#define STAGE_BYTES 32768
#define T_A 0
#define T_B 16384
#define GEMM_SMEM (3 * STAGE_BYTES)

__device__ __forceinline__ void fill_tile64(uint32_t dstbase,
                                            const __half* __restrict__ g,
                                            int row0, int k0, int stride, int tid) {
#pragma unroll
    for (int i = 0; i < 8; ++i) {
        int q = tid + i * 128;
        int r = q >> 3, c = q & 7;
        uint32_t o = (uint32_t)(r * 128 + c * 16);
        cpasync16(dstbase + SW128(o), g + (size_t)(row0 + r) * stride + k0 + c * 8);
    }
}

// ---------------- pre-kernels -----------------------------------------------
__global__ void transpose_E_kernel(const float* __restrict__ E) {
    __shared__ float t[64][33];
    int bx = blockIdx.x, by = blockIdx.y;
    int tx = threadIdx.x, ty = threadIdx.y;        // block (32, 8)
#pragma unroll
    for (int i = 0; i < 8; ++i)
        t[ty + 8 * i][tx] = E[(size_t)(by * 64 + ty + 8 * i) * L + bx * 32 + tx];
    __syncthreads();
#pragma unroll
    for (int i = 0; i < 4; ++i) {
        int ll = ty + 8 * i;
        float v0 = t[2 * tx][ll];
        float v1 = t[2 * tx + 1][ll];
        __half2 hp = __halves2half2(__float2half(v0), __float2half(v1));
        size_t o = (size_t)(bx * 32 + ll) * DE + by * 64 + 2 * tx;
        *reinterpret_cast<__half2*>(&g_Et_h[o]) = hp;
    }
}

__global__ void convert_W_kernel(const float* __restrict__ W) {
    int base = (blockIdx.x * 256 + threadIdx.x) * 8;
    uint32_t pk[4];
#pragma unroll
    for (int h = 0; h < 2; ++h) {
        float4 v = *reinterpret_cast<const float4*>(&W[base + 4 * h]);
        __half2 p0 = __halves2half2(__float2half(v.x), __float2half(v.y));
        __half2 p1 = __halves2half2(__float2half(v.z), __float2half(v.w));
        pk[2 * h]     = *reinterpret_cast<uint32_t*>(&p0);
        pk[2 * h + 1] = *reinterpret_cast<uint32_t*>(&p1);
    }
    *reinterpret_cast<uint4*>(&g_W_h[base]) = make_uint4(pk[0], pk[1], pk[2], pk[3]);
}

// ---------------- radix-16 Stockham FFT, skewed smem -------------------------
#define PHY(i) ((i) + ((i) >> 4))
#define FFT_BUF 8704

template <int INV>
__device__ __forceinline__ void r4_local(float2 a0, float2 a1, float2 a2, float2 a3, float2* y) {
    float2 t0 = cadd(a0, a2), t1 = csub(a0, a2);
    float2 t2 = cadd(a1, a3), t3 = csub(a1, a3);
    float2 jt3 = INV ? make_float2(-t3.y, t3.x) : make_float2(t3.y, -t3.x);
    y[0] = cadd(t0, t2);
    y[1] = cadd(t1, jt3);
    y[2] = csub(t0, t2);
    y[3] = csub(t1, jt3);
}

// DFT-16 in registers: two local radix-4 Stockham stages with omega16 twiddles.
template <int INV>
__device__ __forceinline__ void dft16_reg(const float2* x, float2* X) {
    const float C1 = 0.92387953251128674f;
    const float S1 = 0.38268343236508977f;
    const float C2 = 0.70710678118654752f;
#define MKW(re, im) make_float2((re), INV ? -(im) : (im))
    const float2 W1 = MKW(C1, -S1);
    const float2 W2 = MKW(C2, -C2);
    const float2 W3 = MKW(S1, -C1);
    const float2 W4 = MKW(0.f, -1.f);
    const float2 W6 = MKW(-C2, -C2);
    const float2 W9 = MKW(-C1, S1);
#undef MKW
    float2 y[16];
    float2 b[4];
    r4_local<INV>(x[0], x[4], x[8], x[12], b);
    y[0] = b[0]; y[1] = b[1]; y[2] = b[2]; y[3] = b[3];
    r4_local<INV>(x[1], x[5], x[9], x[13], b);
    y[4] = b[0]; y[5] = cmul(W1, b[1]); y[6] = cmul(W2, b[2]); y[7] = cmul(W3, b[3]);
    r4_local<INV>(x[2], x[6], x[10], x[14], b);
    y[8] = b[0]; y[9] = cmul(W2, b[1]); y[10] = cmul(W4, b[2]); y[11] = cmul(W6, b[3]);
    r4_local<INV>(x[3], x[7], x[11], x[15], b);
    y[12] = b[0]; y[13] = cmul(W3, b[1]); y[14] = cmul(W6, b[2]); y[15] = cmul(W9, b[3]);
    r4_local<INV>(y[0], y[4], y[8], y[12], b);
    X[0] = b[0]; X[4] = b[1]; X[8] = b[2]; X[12] = b[3];
    r4_local<INV>(y[1], y[5], y[9], y[13], b);
    X[1] = b[0]; X[5] = b[1]; X[9] = b[2]; X[13] = b[3];
    r4_local<INV>(y[2], y[6], y[10], y[14], b);
    X[2] = b[0]; X[6] = b[1]; X[10] = b[2]; X[14] = b[3];
    r4_local<INV>(y[3], y[7], y[11], y[15], b);
    X[3] = b[0]; X[7] = b[1]; X[11] = b[2]; X[15] = b[3];
}

// generic radix-16 Stockham stage over smem (512 butterflies)
template <int NT, int INV>
__device__ __forceinline__ void r16_stage(const float2* src, float2* dst, int tid, int m) {
#pragma unroll
    for (int it = 0; it < 512 / NT; ++it) {
        int bf = tid + it * NT;
        int k = bf & (m - 1);
        int u = bf - k;
        float2 x[16];
#pragma unroll
        for (int q = 0; q < 16; ++q) x[q] = src[PHY(bf + q * 512)];
        float2 X[16];
        dft16_reg<INV>(x, X);
        int b16 = 16 * u + k;
        dst[PHY(b16)] = X[0];
#pragma unroll
        for (int j = 1; j < 16; ++j) {
            float2 w = g_tw[j * u];
            if (INV) w.y = -w.y;
            dst[PHY(b16 + j * m)] = cmul(w, X[j]);
        }
    }
    __syncthreads();
}

// fft_F: single CTA; computes g_tw, fwd pipeline of f, writes g_F (pipeline order).
__global__ __launch_bounds__(256) void fft_F_kernel() {
    extern __shared__ float2 sm[];
    float2* A = sm;
    float2* B = sm + FFT_BUF;
    int tid = threadIdx.x;
#pragma unroll
    for (int it = 0; it < 32; ++it) {
        int n = tid + it * 256;
        float s, c;
        sincospif(-2.0f * (float)n / (float)FFT_N, &s, &c);
        g_tw[n] = make_float2(c, s);
    }
    __syncthreads();
    // P1: fwd r16 m=1, f computed on the fly; upper half (q>=8) zero
#pragma unroll
    for (int it = 0; it < 2; ++it) {
        int bf = tid + it * 256;
        float2 x[16];
#pragma unroll
        for (int q = 0; q < 8; ++q) {
            int d = bf + q * 512;
            float v = (d == 0) ? powf(EPSV, HEXP) : powf((float)d * DTF + EPSV, HEXP);
            x[q] = make_float2(v, 0.f);
        }
#pragma unroll
        for (int q = 8; q < 16; ++q) x[q] = make_float2(0.f, 0.f);
        float2 X[16];
        dft16_reg<0>(x, X);
        A[PHY(16 * bf)] = X[0];
#pragma unroll
        for (int j = 1; j < 16; ++j)
            A[PHY(16 * bf + j)] = cmul(g_tw[j * bf], X[j]);
    }
    __syncthreads();
    r16_stage<256, 0>(A, B, tid, 16);
    r16_stage<256, 0>(B, A, tid, 256);
    // final fwd r2 (m=4096, twiddle-free) x 1/N -> g_F
    const float scale = 1.0f / (float)FFT_N;
#pragma unroll
    for (int it = 0; it < 16; ++it) {
        int bf = tid + it * 256;
        float2 a = A[PHY(bf)];
        float2 b = A[PHY(bf + 4096)];
        float2 lo = cadd(a, b);
        float2 hi = csub(a, b);
        g_F[bf] = make_float2(lo.x * scale, lo.y * scale);
        g_F[bf + 4096] = make_float2(hi.x * scale, hi.y * scale);
    }
}

// ---------------- conv: radix-16, 7 passes, NT=512 ---------------------------
#define CONV_NT 512
__global__ __launch_bounds__(CONV_NT) void conv_kernel() {
    extern __shared__ float2 sm[];
    float2* A = sm;
    float2* B = sm + FFT_BUF;
    int tid = threadIdx.x;
    int c2 = blockIdx.x * 2;
    const float* __restrict__ ya = g_Yt + (size_t)c2 * L;
    const float* __restrict__ yb = g_Yt + (size_t)(c2 + 1) * L;

    // P1: fwd r16 m=1 straight from global; q>=8 inputs are zero (padding)
    {
        int bf = tid;
        float2 x[16];
#pragma unroll
        for (int q = 0; q < 8; ++q) {
            int i = bf + q * 512;
            x[q] = make_float2(ya[i], yb[i]);
        }
#pragma unroll
        for (int q = 8; q < 16; ++q) x[q] = make_float2(0.f, 0.f);
        float2 X[16];
        dft16_reg<0>(x, X);
        A[PHY(16 * bf)] = X[0];
#pragma unroll
        for (int j = 1; j < 16; ++j)
            A[PHY(16 * bf + j)] = cmul(g_tw[j * bf], X[j]);
    }
    __syncthreads();
    // P2, P3
    r16_stage<CONV_NT, 0>(A, B, tid, 16);
    r16_stage<CONV_NT, 0>(B, A, tid, 256);
    // P4: fused fwd-r2 (m=4096) x F x inv-r2 (m=1), A -> B
#pragma unroll
    for (int it = 0; it < 4096 / CONV_NT; ++it) {
        int bf = tid + it * CONV_NT;
        float2 a = A[PHY(bf)];
        float2 b = A[PHY(bf + 4096)];
        float2 lo = cmul(cadd(a, b), g_F[bf]);
        float2 hi = cmul(csub(a, b), g_F[bf + 4096]);
        float2 wc = g_tw[bf];
        wc.y = -wc.y;                       // conj for inverse twiddle
        B[PHY(2 * bf)] = cadd(lo, hi);
        B[PHY(2 * bf + 1)] = cmul(wc, csub(lo, hi));
    }
    __syncthreads();
    // P5, P6: inverse r16 stages m=2, m=32
    r16_stage<CONV_NT, 1>(B, A, tid, 2);
    r16_stage<CONV_NT, 1>(A, B, tid, 32);
    // P7: final inverse r16 m=512 (u=0, twiddle-free); only j<8 outputs (<4096)
    float* __restrict__ oa = g_outT + (size_t)c2 * L;
    float* __restrict__ ob = g_outT + (size_t)(c2 + 1) * L;
    {
        int k = tid;
        float2 x[16];
#pragma unroll
        for (int q = 0; q < 16; ++q) x[q] = B[PHY(k + q * 512)];
        float2 X[16];
        dft16_reg<1>(x, X);
#pragma unroll
        for (int j = 0; j < 8; ++j) {
            int o = k + j * 512;
            oa[o] = X[j].x;
            ob[o] = X[j].y;
        }
    }
}

// g_outT [c][i] -> out [i][c]; 64x64 tile, float2 both directions
__global__ void transpose_out_kernel(float* __restrict__ out) {
    __shared__ float2 t2[64][33];
    int i0 = blockIdx.x * 64, c0 = blockIdx.y * 64;
    int tx = threadIdx.x, ty = threadIdx.y;  // (32, 8)
#pragma unroll
    for (int k = 0; k < 8; ++k) {
        int r = ty + 8 * k;
        t2[r][tx] = *reinterpret_cast<const float2*>(&g_outT[(size_t)(c0 + r) * L + i0 + 2 * tx]);
    }
    __syncthreads();
#pragma unroll
    for (int k = 0; k < 8; ++k) {
        int r = ty + 8 * k;
        float2 p0 = t2[2 * tx][r >> 1];
        float2 p1 = t2[2 * tx + 1][r >> 1];
        float2 o;
        o.x = (r & 1) ? p0.y : p0.x;
        o.y = (r & 1) ? p1.y : p1.x;
        *reinterpret_cast<float2*>(&out[(size_t)(i0 + r) * DV + c0 + 2 * tx]) = o;
    }
}

// ---------------- GEMM1 compute: single fp16, warp 64x64, BK=64 --------------
__device__ __forceinline__ void compute_stage64(uint32_t sbase, int lane, int wm, int wn,
                                                float acc[4][8][4]) {
    const int arow = lane & 15;
    const int acolb = (lane >> 4) << 4;
    const int brow = (lane & 7) + ((lane >> 4) << 3);
    const int bcolb = ((lane >> 3) & 1) << 4;
#pragma unroll
    for (int kk = 0; kk < 4; ++kk) {
        uint32_t aF[4][4];
#pragma unroll
        for (int mi = 0; mi < 4; ++mi) {
            uint32_t o = SW128((uint32_t)((wm * 64 + mi * 16 + arow) * 128 + acolb)) ^ (kk << 5);
            ldsm4(aF[mi], sbase + T_A + o);
        }
#pragma unroll
        for (int pi = 0; pi < 4; ++pi) {
            uint32_t bF[4];
            uint32_t o = SW128((uint32_t)((wn * 64 + pi * 16 + brow) * 128 + bcolb)) ^ (kk << 5);
            ldsm4(bF, sbase + T_B + o);
#pragma unroll
            for (int mi = 0; mi < 4; ++mi)
#pragma unroll
                for (int q = 0; q < 2; ++q)
                    mma_fp16(acc[mi][pi * 2 + q], aF[mi], &bF[q * 2]);
        }
    }
}

__global__ __launch_bounds__(128, 2) void gemm1_mma() {
    extern __shared__ char smem[];
    const uint32_t sb = smem_u32(smem);
    const int tid = threadIdx.x, lane = tid & 31, wid = tid >> 5;
    const int wm = wid & 1, wn = (wid >> 1) & 1;
    const int l0 = blockIdx.x * 128;
    const int v0 = blockIdx.y * 128;
    const int KT = DE / 64;

    float acc[4][8][4];
#pragma unroll
    for (int mi = 0; mi < 4; ++mi)
#pragma unroll
        for (int ni = 0; ni < 8; ++ni)
#pragma unroll
            for (int r = 0; r < 4; ++r) acc[mi][ni][r] = 0.f;

#pragma unroll
    for (int s = 0; s < 2; ++s) {
        uint32_t st = sb + s * STAGE_BYTES;
        int k0 = s * 64;
        fill_tile64(st + T_A, g_W_h,  v0, k0, DE, tid);
        fill_tile64(st + T_B, g_Et_h, l0, k0, DE, tid);
        CP_COMMIT();
    }
    for (int kt = 0; kt < KT; ++kt) {
        int ls = kt + 2;
        if (ls < KT) {
            uint32_t st = sb + (ls % 3) * STAGE_BYTES;
            int k0 = ls * 64;
            fill_tile64(st + T_A, g_W_h,  v0, k0, DE, tid);
            fill_tile64(st + T_B, g_Et_h, l0, k0, DE, tid);
        }
        CP_COMMIT();
        CP_WAIT2();
        __syncthreads();
        compute_stage64(sb + (kt % 3) * STAGE_BYTES, lane, wm, wn, acc);
        __syncthreads();
    }

#pragma unroll
    for (int mi = 0; mi < 4; ++mi)
#pragma unroll
        for (int ni = 0; ni < 8; ++ni) {
            const float* c = acc[mi][ni];
            int v_ = v0 + wm * 64 + mi * 16 + (lane >> 2);
            int l_ = l0 + wn * 64 + ni * 8 + 2 * (lane & 3);
#pragma unroll
            for (int h = 0; h < 2; ++h) {
                float2 p;
                p.x = c[2 * h];
                p.y = c[2 * h + 1];
                *reinterpret_cast<float2*>(&g_Yt[(size_t)(v_ + 8 * h) * L + l_]) = p;
            }
        }
}

// ---------------------------------------------------------------------------
#define FFT_SMEM (2 * FFT_BUF * (int)sizeof(float2))

extern "C" void kernel_launch(void* const* d_in, const int* in_sizes, int n_in,
                              void* d_out, int out_size) {
    const float* E = (const float*)d_in[0];   // (1024, 4096)
    const float* W = (const float*)d_in[1];   // (1024, 1024)
    float* out = (float*)d_out;               // (4096, 1024)

    cudaFuncSetAttribute(gemm1_mma, cudaFuncAttributeMaxDynamicSharedMemorySize, GEMM_SMEM);
    cudaFuncSetAttribute(fft_F_kernel, cudaFuncAttributeMaxDynamicSharedMemorySize, FFT_SMEM);
    cudaFuncSetAttribute(conv_kernel, cudaFuncAttributeMaxDynamicSharedMemorySize, FFT_SMEM);

    fft_F_kernel<<<1, 256, FFT_SMEM>>>();
    transpose_E_kernel<<<dim3(L / 32, DE / 64), dim3(32, 8)>>>(E);
    convert_W_kernel<<<(DV * DE) / (256 * 8), 256>>>(W);
    gemm1_mma<<<dim3(L / 128, DV / 128), 128, GEMM_SMEM>>>();
    conv_kernel<<<DV / 2, CONV_NT, FFT_SMEM>>>();
    transpose_out_kernel<<<dim3(L / 64, DV / 64), dim3(32, 8)>>>(out);
}